// round 3
// baseline (speedup 1.0000x reference)
#include <cuda_runtime.h>
#include <math.h>

#define NB 4
#define NC 256
#define NPIX 4096
#define TOTPIX (4096+1024+256+64)

// scratch (allocation-free rule: __device__ globals)
__device__ float g_q[NB*NC*NPIX];            // q projection, CHW
__device__ float g_off[NB*NC*NPIX];          // tanh'd offsets, CHW
__device__ float g_logit[NB*8*16*NPIX];      // logits -> softmax in place
__device__ float g_v[NB*TOTPIX*NC];          // per level: [b][p][c] pixel-major
__device__ float g_agg[NB*NC*NPIX];          // aggregated sampled output, CHW

// ---------------------------------------------------------------------------
// 128x128 SGEMM, 8x8 per thread, double-buffered smem, register prefetch.
// Y = W(256-row major, K=256) * X(K=256 x N), batched over z.
// mode 0: -> g_q (CHW);  mode 1: -> g_v pixel-major;  mode 2: residual+BN+SiLU -> Yp
// ---------------------------------------------------------------------------
__global__ __launch_bounds__(256) void k_gemm128(
    const float* __restrict__ W, const float* __restrict__ X, float* __restrict__ Yp,
    int N, int mode, const float* __restrict__ query,
    const float* __restrict__ gamma, const float* __restrict__ beta,
    const float* __restrict__ mean, const float* __restrict__ var, size_t vbase)
{
    const int K = NC;
    int b = blockIdx.z, m0 = blockIdx.y * 128, n0 = blockIdx.x * 128;
    const float* Xb = (mode == 2) ? (g_agg + (size_t)b * K * N) : (X + (size_t)b * K * N);

    __shared__ float As[2][8][132];
    __shared__ float Bs[2][8][128];

    int tid = threadIdx.x;
    int am = tid >> 1, ak = (tid & 1) * 4;        // A loader: 128 m x 8 k
    int bkr = tid >> 5, bn = (tid & 31) * 4;      // B loader: 8 k x 128 n
    int tx = tid & 15, ty = tid >> 4;             // compute: 16x16 threads
    bool nfull = (n0 + 128 <= N);

    const float* Arow = W + (size_t)(m0 + am) * K;

    float4 ar = *(const float4*)&Arow[ak];
    float br[4];
    if (nfull) {
        float4 t = *(const float4*)&Xb[(size_t)bkr * N + n0 + bn];
        br[0] = t.x; br[1] = t.y; br[2] = t.z; br[3] = t.w;
    } else {
        #pragma unroll
        for (int j = 0; j < 4; j++) {
            int n = n0 + bn + j;
            br[j] = (n < N) ? Xb[(size_t)bkr * N + n] : 0.f;
        }
    }
    As[0][ak+0][am] = ar.x; As[0][ak+1][am] = ar.y;
    As[0][ak+2][am] = ar.z; As[0][ak+3][am] = ar.w;
    Bs[0][bkr][bn+0] = br[0]; Bs[0][bkr][bn+1] = br[1];
    Bs[0][bkr][bn+2] = br[2]; Bs[0][bkr][bn+3] = br[3];
    __syncthreads();

    float acc[8][8];
    #pragma unroll
    for (int i = 0; i < 8; i++)
        #pragma unroll
        for (int j = 0; j < 8; j++) acc[i][j] = 0.f;

    const int NK = K / 8;   // 32
    for (int kt = 0; kt < NK; kt++) {
        int cur = kt & 1;
        if (kt + 1 < NK) {
            int k0 = (kt + 1) * 8;
            ar = *(const float4*)&Arow[k0 + ak];
            if (nfull) {
                float4 t = *(const float4*)&Xb[(size_t)(k0 + bkr) * N + n0 + bn];
                br[0] = t.x; br[1] = t.y; br[2] = t.z; br[3] = t.w;
            } else {
                #pragma unroll
                for (int j = 0; j < 4; j++) {
                    int n = n0 + bn + j;
                    br[j] = (n < N) ? Xb[(size_t)(k0 + bkr) * N + n] : 0.f;
                }
            }
        }
        #pragma unroll
        for (int k = 0; k < 8; k++) {
            float av[8], bv[8];
            *(float4*)&av[0] = *(float4*)&As[cur][k][ty * 4];
            *(float4*)&av[4] = *(float4*)&As[cur][k][64 + ty * 4];
            *(float4*)&bv[0] = *(float4*)&Bs[cur][k][tx * 4];
            *(float4*)&bv[4] = *(float4*)&Bs[cur][k][64 + tx * 4];
            #pragma unroll
            for (int i = 0; i < 8; i++)
                #pragma unroll
                for (int j = 0; j < 8; j++)
                    acc[i][j] += av[i] * bv[j];
        }
        if (kt + 1 < NK) {
            int nx = cur ^ 1;
            As[nx][ak+0][am] = ar.x; As[nx][ak+1][am] = ar.y;
            As[nx][ak+2][am] = ar.z; As[nx][ak+3][am] = ar.w;
            Bs[nx][bkr][bn+0] = br[0]; Bs[nx][bkr][bn+1] = br[1];
            Bs[nx][bkr][bn+2] = br[2]; Bs[nx][bkr][bn+3] = br[3];
        }
        __syncthreads();
    }

    #pragma unroll
    for (int i = 0; i < 8; i++) {
        int m = m0 + ((i < 4) ? (ty * 4 + i) : (64 + ty * 4 + i - 4));
        if (mode == 1) {
            #pragma unroll
            for (int j = 0; j < 8; j++) {
                int n = n0 + ((j < 4) ? (tx * 4 + j) : (64 + tx * 4 + j - 4));
                if (n < N)
                    g_v[vbase + ((size_t)b * N + n) * NC + m] = acc[i][j];
            }
        } else if (mode == 0) {
            float* row = g_q + ((size_t)b * NC + m) * N;
            *(float4*)&row[n0 + tx * 4]      = *(float4*)&acc[i][0];
            *(float4*)&row[n0 + 64 + tx * 4] = *(float4*)&acc[i][4];
        } else {
            float inv = rsqrtf(var[m] + 1e-5f);
            float ga = gamma[m] * inv, be = beta[m], mu = mean[m];
            const float* qrow = query + ((size_t)b * NC + m) * N;
            float* orow = Yp + ((size_t)b * NC + m) * N;
            #pragma unroll
            for (int j = 0; j < 8; j++) {
                int n = n0 + ((j < 4) ? (tx * 4 + j) : (64 + tx * 4 + j - 4));
                float x = acc[i][j] + qrow[n];
                float xn = (x - mu) * ga + be;
                orow[n] = xn / (1.f + __expf(-xn));
            }
        }
    }
}

// ---------------------------------------------------------------------------
// Fused 3x3 conv over g_q: 384 out-ch (256 offsets + 128 logits), implicit
// GEMM K=2304, same 128x128 double-buffered tile. Epilogue: bias + tanh*0.25
// on offset tiles, bias only on logit tile (tiles are channel-uniform).
// ---------------------------------------------------------------------------
__global__ __launch_bounds__(256) void k_conv128(
    const float* __restrict__ off_w, const float* __restrict__ attn_w,
    const float* __restrict__ off_b, const float* __restrict__ attn_b)
{
    const int K = 2304;
    int b = blockIdx.z, m0 = blockIdx.y * 128, n0 = blockIdx.x * 128;
    const float* Q = g_q + (size_t)b * NC * NPIX;
    const float* Wb = (m0 < 256) ? (off_w + (size_t)m0 * K)
                                 : (attn_w + (size_t)(m0 - 256) * K);

    __shared__ float As[2][8][132];
    __shared__ float Bs[2][8][128];

    int tid = threadIdx.x;
    int am = tid >> 1, ak = (tid & 1) * 4;
    int bkr = tid >> 5, bn = (tid & 31) * 4;
    int tx = tid & 15, ty = tid >> 4;

    const float* Arow = Wb + (size_t)am * K;

    int px4[4], py4[4];
    #pragma unroll
    for (int j = 0; j < 4; j++) {
        int p = n0 + bn + j;
        py4[j] = p >> 6; px4[j] = p & 63;
    }

    int cch = 0, tap = bkr;   // kg = kt*8 + bkr = cch*9 + tap
    float4 ar = *(const float4*)&Arow[ak];
    float br[4];
    {
        int dy = (tap >= 6) ? 1 : ((tap >= 3) ? 0 : -1);
        int dx = tap - (dy + 1) * 3 - 1;
        #pragma unroll
        for (int j = 0; j < 4; j++) {
            int sy = py4[j] + dy, sx = px4[j] + dx;
            br[j] = ((unsigned)sy < 64u && (unsigned)sx < 64u)
                        ? Q[(size_t)cch * NPIX + sy * 64 + sx] : 0.f;
        }
    }
    As[0][ak+0][am] = ar.x; As[0][ak+1][am] = ar.y;
    As[0][ak+2][am] = ar.z; As[0][ak+3][am] = ar.w;
    Bs[0][bkr][bn+0] = br[0]; Bs[0][bkr][bn+1] = br[1];
    Bs[0][bkr][bn+2] = br[2]; Bs[0][bkr][bn+3] = br[3];
    __syncthreads();

    float acc[8][8];
    #pragma unroll
    for (int i = 0; i < 8; i++)
        #pragma unroll
        for (int j = 0; j < 8; j++) acc[i][j] = 0.f;

    const int NK = K / 8;   // 288
    for (int kt = 0; kt < NK; kt++) {
        int cur = kt & 1;
        if (kt + 1 < NK) {
            ar = *(const float4*)&Arow[(kt + 1) * 8 + ak];
            tap += 8; if (tap >= 9) { tap -= 9; cch++; }
            int dy = (tap >= 6) ? 1 : ((tap >= 3) ? 0 : -1);
            int dx = tap - (dy + 1) * 3 - 1;
            #pragma unroll
            for (int j = 0; j < 4; j++) {
                int sy = py4[j] + dy, sx = px4[j] + dx;
                br[j] = ((unsigned)sy < 64u && (unsigned)sx < 64u)
                            ? Q[(size_t)cch * NPIX + sy * 64 + sx] : 0.f;
            }
        }
        #pragma unroll
        for (int k = 0; k < 8; k++) {
            float av[8], bv[8];
            *(float4*)&av[0] = *(float4*)&As[cur][k][ty * 4];
            *(float4*)&av[4] = *(float4*)&As[cur][k][64 + ty * 4];
            *(float4*)&bv[0] = *(float4*)&Bs[cur][k][tx * 4];
            *(float4*)&bv[4] = *(float4*)&Bs[cur][k][64 + tx * 4];
            #pragma unroll
            for (int i = 0; i < 8; i++)
                #pragma unroll
                for (int j = 0; j < 8; j++)
                    acc[i][j] += av[i] * bv[j];
        }
        if (kt + 1 < NK) {
            int nx = cur ^ 1;
            As[nx][ak+0][am] = ar.x; As[nx][ak+1][am] = ar.y;
            As[nx][ak+2][am] = ar.z; As[nx][ak+3][am] = ar.w;
            Bs[nx][bkr][bn+0] = br[0]; Bs[nx][bkr][bn+1] = br[1];
            Bs[nx][bkr][bn+2] = br[2]; Bs[nx][bkr][bn+3] = br[3];
        }
        __syncthreads();
    }

    bool isoff = (m0 < 256);
    #pragma unroll
    for (int i = 0; i < 8; i++) {
        int m = m0 + ((i < 4) ? (ty * 4 + i) : (64 + ty * 4 + i - 4));
        if (isoff) {
            float bias = off_b[m];
            float* row = g_off + ((size_t)b * NC + m) * NPIX;
            #pragma unroll
            for (int j = 0; j < 8; j++) {
                int n = n0 + ((j < 4) ? (tx * 4 + j) : (64 + tx * 4 + j - 4));
                row[n] = tanhf(acc[i][j] + bias) * 0.25f;
            }
        } else {
            float bias = attn_b[m - 256];
            float* row = g_logit + ((size_t)b * 128 + (m - 256)) * NPIX;
            #pragma unroll
            for (int j = 0; j < 8; j++) {
                int n = n0 + ((j < 4) ? (tx * 4 + j) : (64 + tx * 4 + j - 4));
                row[n] = acc[i][j] + bias;
            }
        }
    }
}

// softmax over the 16 (level,point) logits per (b, head, pixel); in place.
__global__ void k_softmax()
{
    int t = blockIdx.x * blockDim.x + threadIdx.x;
    int p = t & (NPIX - 1);
    int r = t >> 12;
    float* base = g_logit + (size_t)r * 16 * NPIX + p;
    float vals[16];
    float mx = -1e30f;
    #pragma unroll
    for (int i = 0; i < 16; i++) { vals[i] = base[(size_t)i * NPIX]; mx = fmaxf(mx, vals[i]); }
    float s = 0.f;
    #pragma unroll
    for (int i = 0; i < 16; i++) { vals[i] = __expf(vals[i] - mx); s += vals[i]; }
    float inv = 1.f / s;
    #pragma unroll
    for (int i = 0; i < 16; i++) base[(size_t)i * NPIX] = vals[i] * inv;
}

// ---------------------------------------------------------------------------
// Deformable sampling. One warp per query pixel; lane = head-dim channel.
// ---------------------------------------------------------------------------
__global__ void k_sample()
{
    int bh = blockIdx.y;
    int b = bh >> 3, h = bh & 7;
    int p0 = blockIdx.x * 32;
    int warp = threadIdx.x >> 5, lane = threadIdx.x & 31;
    int p = p0 + warp;
    int py = p >> 6, px = p & 63;
    float refx = -1.f + 2.f * px / 63.f;
    float refy = -1.f + 2.f * py / 63.f;

    const float* offb = g_off + (size_t)b * NC * NPIX + p;
    const float* attb = g_logit + (size_t)(b * 8 + h) * 16 * NPIX + p;

    float acc = 0.f;
    size_t base = 0;
    int wl = 64;
    #pragma unroll
    for (int lvl = 0; lvl < 4; lvl++) {
        int npix = wl * wl;
        const float* vb = g_v + base + (size_t)b * npix * NC + h * 32 + lane;
        float sw = 0.5f * (wl - 1);
        #pragma unroll
        for (int pt = 0; pt < 4; pt++) {
            int cho = ((h * 4 + lvl) * 4 + pt) * 2;
            float ox = offb[(size_t)cho * NPIX];
            float oy = offb[(size_t)(cho + 1) * NPIX];
            float a  = attb[(size_t)(lvl * 4 + pt) * NPIX];
            float fx = (refx + ox + 1.f) * sw;
            float fy = (refy + oy + 1.f) * sw;
            float x0f = floorf(fx), y0f = floorf(fy);
            float wx1 = fx - x0f, wx0 = 1.f - wx1;
            float wy1 = fy - y0f, wy0 = 1.f - wy1;
            int x0 = (int)x0f, y0 = (int)y0f;
            int x1 = x0 + 1, y1 = y0 + 1;
            float sv = 0.f;
            if (x0 >= 0 && x0 < wl && y0 >= 0 && y0 < wl) sv += wx0 * wy0 * vb[(size_t)(y0 * wl + x0) * NC];
            if (x1 >= 0 && x1 < wl && y0 >= 0 && y0 < wl) sv += wx1 * wy0 * vb[(size_t)(y0 * wl + x1) * NC];
            if (x0 >= 0 && x0 < wl && y1 >= 0 && y1 < wl) sv += wx0 * wy1 * vb[(size_t)(y1 * wl + x0) * NC];
            if (x1 >= 0 && x1 < wl && y1 >= 0 && y1 < wl) sv += wx1 * wy1 * vb[(size_t)(y1 * wl + x1) * NC];
            acc += a * sv;
        }
        base += (size_t)NB * npix * NC;
        wl >>= 1;
    }

    __shared__ float s[32][33];
    s[warp][lane] = acc;
    __syncthreads();
    g_agg[((size_t)b * NC + h * 32 + warp) * NPIX + p0 + lane] = s[lane][warp];
}

extern "C" void kernel_launch(void* const* d_in, const int* in_sizes, int n_in,
                              void* d_out, int out_size)
{
    const float* query  = (const float*)d_in[0];
    const float* feat[4] = {(const float*)d_in[1], (const float*)d_in[2],
                            (const float*)d_in[3], (const float*)d_in[4]};
    const float* q_w    = (const float*)d_in[5];
    const float* v_w    = (const float*)d_in[6];
    const float* out_w  = (const float*)d_in[7];
    const float* off_w  = (const float*)d_in[8];
    const float* off_b  = (const float*)d_in[9];
    const float* attn_w = (const float*)d_in[10];
    const float* attn_b = (const float*)d_in[11];
    const float* gamma  = (const float*)d_in[12];
    const float* beta   = (const float*)d_in[13];
    const float* mean   = (const float*)d_in[14];
    const float* var    = (const float*)d_in[15];

    dim3 blk(256);

    // 1. q projection
    k_gemm128<<<dim3(32, 2, NB), blk>>>(q_w, query, nullptr, NPIX, 0,
                                        nullptr, nullptr, nullptr, nullptr, nullptr, 0);
    // 2. fused 3x3 conv (offsets + logits)
    k_conv128<<<dim3(32, 3, NB), blk>>>(off_w, attn_w, off_b, attn_b);
    // 3. softmax over level*point
    k_softmax<<<512, 256>>>();
    // 4. v projections per level (pixel-major layout)
    size_t vbase = 0;
    for (int lvl = 0; lvl < 4; lvl++) {
        int wl = 64 >> lvl;
        int np = wl * wl;
        k_gemm128<<<dim3((np + 127) / 128, 2, NB), blk>>>(v_w + (size_t)lvl * 256 * 256, feat[lvl],
                                                          nullptr, np, 1,
                                                          nullptr, nullptr, nullptr, nullptr, nullptr,
                                                          vbase);
        vbase += (size_t)NB * np * NC;
    }
    // 5. deformable sampling + aggregation
    k_sample<<<dim3(128, 32), 1024>>>();
    // 6. output projection + residual + BN + SiLU
    k_gemm128<<<dim3(32, 2, NB), blk>>>(out_w, nullptr, (float*)d_out, NPIX, 2,
                                        query, gamma, beta, mean, var, 0);
}